// round 2
// baseline (speedup 1.0000x reference)
#include <cuda_runtime.h>
#include <math.h>
#include <stdint.h>

// Problem constants (fixed shapes)
#define T_TOK 2048     // B*S tokens
#define HID   2048     // hidden size H
#define INTD  1024     // intermediate size I
#define NE    32       // experts
#define TOPK  4
#define MAXTILES 256

// ---------------- device scratch (static; no runtime alloc) ----------------
__device__ int   g_cnt[NE];
__device__ int   g_tok[NE * T_TOK];
__device__ float g_w  [NE * T_TOK];
__device__ int   g_off[NE + 1];
__device__ int   g_tile_e[MAXTILES];
__device__ int   g_tile_s[MAXTILES];
__device__ int   g_ntiles;
__device__ __align__(16) float g_hid[T_TOK * TOPK * INTD];  // routed hidden, 32MB
__device__ __align__(16) float g_hs [T_TOK * INTD];         // shared-expert hidden, 8MB

// ---------------- zero counters ----------------
__global__ void zero_kernel() {
    if (threadIdx.x < NE) g_cnt[threadIdx.x] = 0;
}

// ---------------- router: logits + sigmoid + top-4 + list build ----------------
// block: 256 threads = 8 warps, one token per warp. grid: T_TOK/8
__global__ void __launch_bounds__(256)
router_kernel(const float* __restrict__ x,
              const float* __restrict__ rw,
              const float* __restrict__ bias) {
    __shared__ float rwS[32][65];   // padded: bank-conflict-free column reads
    __shared__ float xS[8][64];
    int warp = threadIdx.x >> 5, lane = threadIdx.x & 31;
    int t = blockIdx.x * 8 + warp;

    float acc = 0.f;
    for (int h0 = 0; h0 < HID; h0 += 64) {
        __syncthreads();
        for (int i = threadIdx.x; i < 32 * 64; i += 256) {
            int e = i >> 6, j = i & 63;
            rwS[e][j] = rw[e * HID + h0 + j];
        }
        xS[warp][lane]      = x[(size_t)t * HID + h0 + lane];
        xS[warp][lane + 32] = x[(size_t)t * HID + h0 + 32 + lane];
        __syncthreads();
        #pragma unroll 8
        for (int j = 0; j < 64; j++)
            acc += xS[warp][j] * rwS[lane][j];
    }
    // lane == expert index
    float score = 1.f / (1.f + __expf(-acc));
    float selv  = score + bias[lane];

    int   picks[TOPK];
    float pw[TOPK];
    float wsum = 0.f;
    #pragma unroll
    for (int k = 0; k < TOPK; k++) {
        float v = selv; int idx = lane;
        #pragma unroll
        for (int o = 16; o > 0; o >>= 1) {
            float v2 = __shfl_xor_sync(0xFFFFFFFFu, v, o);
            int   i2 = __shfl_xor_sync(0xFFFFFFFFu, idx, o);
            if (v2 > v || (v2 == v && i2 < idx)) { v = v2; idx = i2; }
        }
        picks[k] = idx;
        float w = __shfl_sync(0xFFFFFFFFu, score, idx);
        pw[k] = w;
        wsum += w;
        if (lane == idx) selv = -INFINITY;
    }
    if (lane == 0) {
        float inv = 1.f / (wsum + 1e-20f);  // RSF = 1.0
        #pragma unroll
        for (int k = 0; k < TOPK; k++) {
            int e = picks[k];
            int pos = atomicAdd(&g_cnt[e], 1);
            g_tok[e * T_TOK + pos] = t;
            g_w  [e * T_TOK + pos] = pw[k] * inv;
        }
    }
}

// ---------------- tile scheduler ----------------
__global__ void build_tiles_kernel() {
    if (threadIdx.x == 0 && blockIdx.x == 0) {
        int off = 0, nt = 0;
        for (int e = 0; e < NE; e++) {
            g_off[e] = off;
            int c = g_cnt[e];
            for (int s = 0; s < c; s += 64) {
                g_tile_e[nt] = e;
                g_tile_s[nt] = s;
                nt++;
            }
            off += c;
        }
        g_off[NE] = off;
        g_ntiles = nt;
    }
}

// ---------------- grouped GEMM: gate+up, fused SiLU, routed ----------------
// BM=64 BN=64 BK=16, 256 thr, 4x4 micro-tile
__global__ void __launch_bounds__(256)
gateup_routed(const float* __restrict__ x,
              const float* __restrict__ wg_all,
              const float* __restrict__ wu_all) {
    int tile = blockIdx.x;
    if (tile >= g_ntiles) return;
    int e = g_tile_e[tile];
    int s = g_tile_s[tile];
    int rows = min(64, g_cnt[e] - s);
    int hidbase = g_off[e] + s;
    const float* wg = wg_all + (size_t)e * HID * INTD;
    const float* wu = wu_all + (size_t)e * HID * INTD;
    int n0blk = blockIdx.y * 64;

    __shared__ float As[16][68];
    __shared__ float Bg[16][64];
    __shared__ float Bu[16][64];
    __shared__ int rowTok[64];

    int tid = threadIdx.x;
    if (tid < 64)
        rowTok[tid] = g_tok[e * T_TOK + s + ((tid < rows) ? tid : 0)];
    __syncthreads();

    int aRow = tid >> 2, aK4 = (tid & 3) * 4;
    int bK = tid >> 4,  bN = (tid & 15) * 4;
    int tx = tid & 15,  ty = tid >> 4;
    int m0 = ty * 4, n0 = tx * 4;
    int tok = rowTok[aRow];

    float accG[4][4] = {}, accU[4][4] = {};

    for (int k0 = 0; k0 < HID; k0 += 16) {
        float4 av = *(const float4*)&x[(size_t)tok * HID + k0 + aK4];
        float4 bg = *(const float4*)&wg[(size_t)(k0 + bK) * INTD + n0blk + bN];
        float4 bu = *(const float4*)&wu[(size_t)(k0 + bK) * INTD + n0blk + bN];
        As[aK4 + 0][aRow] = av.x;
        As[aK4 + 1][aRow] = av.y;
        As[aK4 + 2][aRow] = av.z;
        As[aK4 + 3][aRow] = av.w;
        *(float4*)&Bg[bK][bN] = bg;
        *(float4*)&Bu[bK][bN] = bu;
        __syncthreads();
        #pragma unroll
        for (int kk = 0; kk < 16; kk++) {
            float4 a = *(const float4*)&As[kk][m0];
            float4 g = *(const float4*)&Bg[kk][n0];
            float4 u = *(const float4*)&Bu[kk][n0];
            float am[4] = {a.x, a.y, a.z, a.w};
            float gv[4] = {g.x, g.y, g.z, g.w};
            float uv[4] = {u.x, u.y, u.z, u.w};
            #pragma unroll
            for (int i = 0; i < 4; i++)
                #pragma unroll
                for (int j = 0; j < 4; j++) {
                    accG[i][j] += am[i] * gv[j];
                    accU[i][j] += am[i] * uv[j];
                }
        }
        __syncthreads();
    }
    #pragma unroll
    for (int i = 0; i < 4; i++) {
        int m = m0 + i;
        if (m < rows) {
            float4 r;
            float* rp = (float*)&r;
            #pragma unroll
            for (int j = 0; j < 4; j++) {
                float g = accG[i][j], u = accU[i][j];
                rp[j] = (g / (1.f + __expf(-g))) * u;
            }
            *(float4*)&g_hid[(size_t)(hidbase + m) * INTD + n0blk + n0] = r;
        }
    }
}

// ---------------- dense gate+up for shared expert ----------------
__global__ void __launch_bounds__(256)
gateup_shared(const float* __restrict__ x,
              const float* __restrict__ wg,
              const float* __restrict__ wu) {
    int mblk = blockIdx.x * 64;
    int n0blk = blockIdx.y * 64;

    __shared__ float As[16][68];
    __shared__ float Bg[16][64];
    __shared__ float Bu[16][64];

    int tid = threadIdx.x;
    int aRow = tid >> 2, aK4 = (tid & 3) * 4;
    int bK = tid >> 4,  bN = (tid & 15) * 4;
    int tx = tid & 15,  ty = tid >> 4;
    int m0 = ty * 4, n0 = tx * 4;
    int tok = mblk + aRow;

    float accG[4][4] = {}, accU[4][4] = {};

    for (int k0 = 0; k0 < HID; k0 += 16) {
        float4 av = *(const float4*)&x[(size_t)tok * HID + k0 + aK4];
        float4 bg = *(const float4*)&wg[(size_t)(k0 + bK) * INTD + n0blk + bN];
        float4 bu = *(const float4*)&wu[(size_t)(k0 + bK) * INTD + n0blk + bN];
        As[aK4 + 0][aRow] = av.x;
        As[aK4 + 1][aRow] = av.y;
        As[aK4 + 2][aRow] = av.z;
        As[aK4 + 3][aRow] = av.w;
        *(float4*)&Bg[bK][bN] = bg;
        *(float4*)&Bu[bK][bN] = bu;
        __syncthreads();
        #pragma unroll
        for (int kk = 0; kk < 16; kk++) {
            float4 a = *(const float4*)&As[kk][m0];
            float4 g = *(const float4*)&Bg[kk][n0];
            float4 u = *(const float4*)&Bu[kk][n0];
            float am[4] = {a.x, a.y, a.z, a.w};
            float gv[4] = {g.x, g.y, g.z, g.w};
            float uv[4] = {u.x, u.y, u.z, u.w};
            #pragma unroll
            for (int i = 0; i < 4; i++)
                #pragma unroll
                for (int j = 0; j < 4; j++) {
                    accG[i][j] += am[i] * gv[j];
                    accU[i][j] += am[i] * uv[j];
                }
        }
        __syncthreads();
    }
    #pragma unroll
    for (int i = 0; i < 4; i++) {
        int m = mblk + m0 + i;
        float4 r;
        float* rp = (float*)&r;
        #pragma unroll
        for (int j = 0; j < 4; j++) {
            float g = accG[i][j], u = accU[i][j];
            rp[j] = (g / (1.f + __expf(-g))) * u;
        }
        *(float4*)&g_hs[(size_t)m * INTD + n0blk + n0] = r;
    }
}

// ---------------- dense down-proj, shared expert: writes out ----------------
__global__ void __launch_bounds__(256)
down_shared(const float* __restrict__ wd, float* __restrict__ out) {
    int mblk = blockIdx.x * 64;
    int n0blk = blockIdx.y * 64;

    __shared__ float As[16][68];
    __shared__ float Bs[16][64];

    int tid = threadIdx.x;
    int aRow = tid >> 2, aK4 = (tid & 3) * 4;
    int bK = tid >> 4,  bN = (tid & 15) * 4;
    int tx = tid & 15,  ty = tid >> 4;
    int m0 = ty * 4, n0 = tx * 4;

    float acc[4][4] = {};

    for (int k0 = 0; k0 < INTD; k0 += 16) {
        float4 av = *(const float4*)&g_hs[(size_t)(mblk + aRow) * INTD + k0 + aK4];
        float4 bv = *(const float4*)&wd[(size_t)(k0 + bK) * HID + n0blk + bN];
        As[aK4 + 0][aRow] = av.x;
        As[aK4 + 1][aRow] = av.y;
        As[aK4 + 2][aRow] = av.z;
        As[aK4 + 3][aRow] = av.w;
        *(float4*)&Bs[bK][bN] = bv;
        __syncthreads();
        #pragma unroll
        for (int kk = 0; kk < 16; kk++) {
            float4 a = *(const float4*)&As[kk][m0];
            float4 b = *(const float4*)&Bs[kk][n0];
            float am[4] = {a.x, a.y, a.z, a.w};
            float bw[4] = {b.x, b.y, b.z, b.w};
            #pragma unroll
            for (int i = 0; i < 4; i++)
                #pragma unroll
                for (int j = 0; j < 4; j++)
                    acc[i][j] += am[i] * bw[j];
        }
        __syncthreads();
    }
    #pragma unroll
    for (int i = 0; i < 4; i++) {
        int m = mblk + m0 + i;
        float4 r = make_float4(acc[i][0], acc[i][1], acc[i][2], acc[i][3]);
        *(float4*)&out[(size_t)m * HID + n0blk + n0] = r;
    }
}

// ---------------- grouped down-proj, routed: atomic scatter into out ----------------
__global__ void __launch_bounds__(256)
down_routed(const float* __restrict__ wd_all, float* __restrict__ out) {
    int tile = blockIdx.x;
    if (tile >= g_ntiles) return;
    int e = g_tile_e[tile];
    int s = g_tile_s[tile];
    int rows = min(64, g_cnt[e] - s);
    int hidbase = g_off[e] + s;
    const float* wd = wd_all + (size_t)e * INTD * HID;
    int n0blk = blockIdx.y * 64;

    __shared__ float As[16][68];
    __shared__ float Bs[16][64];
    __shared__ int rowTok[64];
    __shared__ float rowW[64];

    int tid = threadIdx.x;
    if (tid < 64) {
        int idx = (tid < rows) ? tid : 0;
        rowTok[tid] = g_tok[e * T_TOK + s + idx];
        rowW[tid]   = g_w  [e * T_TOK + s + idx];
    }
    __syncthreads();

    int aRow = tid >> 2, aK4 = (tid & 3) * 4;
    // FIX (R1 illegal access): clamp A-load row for partial tiles; rows beyond
    // `rows` would index g_hid past g_off[NE]*INTD (OOB). Their products are
    // discarded by the m<rows guard below, so reading row 0 is safe.
    int aRowC = (aRow < rows) ? aRow : 0;
    int bK = tid >> 4,  bN = (tid & 15) * 4;
    int tx = tid & 15,  ty = tid >> 4;
    int m0 = ty * 4, n0 = tx * 4;

    float acc[4][4] = {};

    for (int k0 = 0; k0 < INTD; k0 += 16) {
        float4 av = *(const float4*)&g_hid[(size_t)(hidbase + aRowC) * INTD + k0 + aK4];
        float4 bv = *(const float4*)&wd[(size_t)(k0 + bK) * HID + n0blk + bN];
        As[aK4 + 0][aRow] = av.x;
        As[aK4 + 1][aRow] = av.y;
        As[aK4 + 2][aRow] = av.z;
        As[aK4 + 3][aRow] = av.w;
        *(float4*)&Bs[bK][bN] = bv;
        __syncthreads();
        #pragma unroll
        for (int kk = 0; kk < 16; kk++) {
            float4 a = *(const float4*)&As[kk][m0];
            float4 b = *(const float4*)&Bs[kk][n0];
            float am[4] = {a.x, a.y, a.z, a.w};
            float bw[4] = {b.x, b.y, b.z, b.w};
            #pragma unroll
            for (int i = 0; i < 4; i++)
                #pragma unroll
                for (int j = 0; j < 4; j++)
                    acc[i][j] += am[i] * bw[j];
        }
        __syncthreads();
    }
    #pragma unroll
    for (int i = 0; i < 4; i++) {
        int m = m0 + i;
        if (m < rows) {
            int tok = rowTok[m];
            float w = rowW[m];
            float* dst = &out[(size_t)tok * HID + n0blk + n0];
            #pragma unroll
            for (int j = 0; j < 4; j++)
                atomicAdd(&dst[j], acc[i][j] * w);
        }
    }
}

// ---------------- launch ----------------
extern "C" void kernel_launch(void* const* d_in, const int* in_sizes, int n_in,
                              void* d_out, int out_size) {
    const float* x    = (const float*)d_in[0];
    const float* rw   = (const float*)d_in[1];
    const float* bias = (const float*)d_in[2];
    const float* wg   = (const float*)d_in[3];
    const float* wu   = (const float*)d_in[4];
    const float* wd   = (const float*)d_in[5];
    const float* swg  = (const float*)d_in[6];
    const float* swu  = (const float*)d_in[7];
    const float* swd  = (const float*)d_in[8];
    float* out = (float*)d_out;

    zero_kernel<<<1, 32>>>();
    router_kernel<<<T_TOK / 8, 256>>>(x, rw, bias);
    build_tiles_kernel<<<1, 32>>>();

    // shared expert (dense) + routed experts (grouped)
    gateup_shared<<<dim3(T_TOK / 64, INTD / 64), 256>>>(x, swg, swu);
    gateup_routed<<<dim3(192, INTD / 64), 256>>>(x, wg, wu);

    down_shared<<<dim3(T_TOK / 64, HID / 64), 256>>>(swd, out);   // writes out
    down_routed<<<dim3(192, HID / 64), 256>>>(wd, out);           // atomic accumulate
}

// round 4
// speedup vs baseline: 2.4057x; 2.4057x over previous
#include <cuda_runtime.h>
#include <cuda_bf16.h>
#include <math.h>
#include <stdint.h>

#define T_TOK 2048
#define HID   2048
#define INTD  1024
#define NE    32
#define NE_TOT 33
#define TOPK  4
#define MAXTILES 128
#define BM    128
#define ROWS_MAX 10368   // 8192 routed + 2048 shared + pad

// ===================== device scratch =====================
__device__ int   g_cnt[NE_TOT];
__device__ int   g_tok[NE_TOT * T_TOK];
__device__ float g_w  [NE_TOT * T_TOK];
__device__ int   g_off[NE_TOT + 1];
__device__ int   g_tile_e[MAXTILES];
__device__ int   g_tile_s[MAXTILES];
__device__ int   g_ntiles;
__device__ __align__(16) float g_gu[(size_t)ROWS_MAX * 2048];  // gate|up fp32
__device__ __align__(16) float g_h [(size_t)ROWS_MAX * 1024];  // silu(g)*u fp32

// ===================== PTX helpers (family-level, sm_80+) =====================
__device__ __forceinline__ uint32_t smem_u32(const void* p) {
    uint32_t a;
    asm("{ .reg .u64 t; cvta.to.shared.u64 t, %1; cvt.u32.u64 %0, t; }" : "=r"(a) : "l"(p));
    return a;
}
__device__ __forceinline__ void ldsm_x4(uint32_t* r, uint32_t a) {
    asm volatile("ldmatrix.sync.aligned.m8n8.x4.shared.b16 {%0,%1,%2,%3}, [%4];"
                 : "=r"(r[0]), "=r"(r[1]), "=r"(r[2]), "=r"(r[3]) : "r"(a));
}
__device__ __forceinline__ void ldsm_x4_t(uint32_t* r, uint32_t a) {
    asm volatile("ldmatrix.sync.aligned.m8n8.x4.trans.shared.b16 {%0,%1,%2,%3}, [%4];"
                 : "=r"(r[0]), "=r"(r[1]), "=r"(r[2]), "=r"(r[3]) : "r"(a));
}
__device__ __forceinline__ void mma_bf16(float* c, const uint32_t* a, const uint32_t* b) {
    asm volatile("mma.sync.aligned.m16n8k16.row.col.f32.bf16.bf16.f32 "
        "{%0,%1,%2,%3}, {%4,%5,%6,%7}, {%8,%9}, {%0,%1,%2,%3};"
        : "+f"(c[0]), "+f"(c[1]), "+f"(c[2]), "+f"(c[3])
        : "r"(a[0]), "r"(a[1]), "r"(a[2]), "r"(a[3]), "r"(b[0]), "r"(b[1]));
}
// split fp32x4 -> bf16 hi (8B) + lo (8B)
__device__ __forceinline__ void split4(float4 f, uint2& hi, uint2& lo) {
    __nv_bfloat16 a0 = __float2bfloat16(f.x), a1 = __float2bfloat16(f.y);
    __nv_bfloat16 a2 = __float2bfloat16(f.z), a3 = __float2bfloat16(f.w);
    __nv_bfloat16 b0 = __float2bfloat16(f.x - __bfloat162float(a0));
    __nv_bfloat16 b1 = __float2bfloat16(f.y - __bfloat162float(a1));
    __nv_bfloat16 b2 = __float2bfloat16(f.z - __bfloat162float(a2));
    __nv_bfloat16 b3 = __float2bfloat16(f.w - __bfloat162float(a3));
    __nv_bfloat162 h01(a0, a1), h23(a2, a3), l01(b0, b1), l23(b2, b3);
    hi = make_uint2(*(uint32_t*)&h01, *(uint32_t*)&h23);
    lo = make_uint2(*(uint32_t*)&l01, *(uint32_t*)&l23);
}

// ===================== small kernels =====================
__global__ void zero_kernel() {
    int t = threadIdx.x;
    if (t < NE) g_cnt[t] = 0;
    if (t == NE) g_cnt[NE] = T_TOK;
}

__global__ void __launch_bounds__(256)
router_kernel(const float* __restrict__ x,
              const float* __restrict__ rw,
              const float* __restrict__ bias) {
    __shared__ float rwS[32][65];
    __shared__ float xS[8][64];
    int warp = threadIdx.x >> 5, lane = threadIdx.x & 31;
    int t = blockIdx.x * 8 + warp;

    float acc = 0.f;
    for (int h0 = 0; h0 < HID; h0 += 64) {
        __syncthreads();
        for (int i = threadIdx.x; i < 32 * 64; i += 256) {
            int e = i >> 6, j = i & 63;
            rwS[e][j] = rw[e * HID + h0 + j];
        }
        xS[warp][lane]      = x[(size_t)t * HID + h0 + lane];
        xS[warp][lane + 32] = x[(size_t)t * HID + h0 + 32 + lane];
        __syncthreads();
        #pragma unroll 8
        for (int j = 0; j < 64; j++)
            acc += xS[warp][j] * rwS[lane][j];
    }
    float score = 1.f / (1.f + __expf(-acc));
    float selv  = score + bias[lane];

    int   picks[TOPK];
    float pw[TOPK];
    float wsum = 0.f;
    #pragma unroll
    for (int k = 0; k < TOPK; k++) {
        float v = selv; int idx = lane;
        #pragma unroll
        for (int o = 16; o > 0; o >>= 1) {
            float v2 = __shfl_xor_sync(0xFFFFFFFFu, v, o);
            int   i2 = __shfl_xor_sync(0xFFFFFFFFu, idx, o);
            if (v2 > v || (v2 == v && i2 < idx)) { v = v2; idx = i2; }
        }
        picks[k] = idx;
        float w = __shfl_sync(0xFFFFFFFFu, score, idx);
        pw[k] = w; wsum += w;
        if (lane == idx) selv = -INFINITY;
    }
    if (lane == 0) {
        float inv = 1.f / (wsum + 1e-20f);
        #pragma unroll
        for (int k = 0; k < TOPK; k++) {
            int e = picks[k];
            int pos = atomicAdd(&g_cnt[e], 1);
            g_tok[e * T_TOK + pos] = t;
            g_w  [e * T_TOK + pos] = pw[k] * inv;
        }
        g_tok[NE * T_TOK + t] = t;   // shared expert identity routing
        g_w  [NE * T_TOK + t] = 1.0f;
    }
}

__global__ void build_tiles_kernel() {
    if (threadIdx.x == 0 && blockIdx.x == 0) {
        int off = 0, nt = 0;
        for (int e = 0; e < NE_TOT; e++) {
            g_off[e] = off;
            int c = g_cnt[e];
            for (int s = 0; s < c && nt < MAXTILES; s += BM) {
                g_tile_e[nt] = e; g_tile_s[nt] = s; nt++;
            }
            off += c;
        }
        g_off[NE_TOT] = off;
        g_ntiles = nt;
    }
}

// ===================== grouped GEMM via mma.sync bf16, 3-pass split =====================
// MODE 0: A = x rows (gathered by rowTok), K=2048, B = wg|wu combined N=2048,
//         epilogue -> g_gu fp32
// MODE 1: A = g_h rows (direct), K=1024, B = wd, N=2048,
//         epilogue -> atomicAdd(out, d * w)
template<int MODE>
__global__ void __launch_bounds__(256, 1)
moe_gemm(const float* __restrict__ x,
         const float* __restrict__ B0, const float* __restrict__ B1,
         const float* __restrict__ B2, const float* __restrict__ B3,
         float* __restrict__ out) {
    constexpr int K    = MODE ? 1024 : 2048;
    constexpr int KCH  = K / 32;
    constexpr int ASTR = MODE ? 1024 : 2048;
    constexpr int BSTR = MODE ? 2048 : 1024;

    __shared__ __align__(16) char sm[1024 + 16384 + 16384];
    int* rowTokS = (int*)sm;
    float* rowWS = (float*)(sm + 512);
    char* Asm = sm + 1024;
    char* Bsm = sm + 1024 + 16384;
    uint32_t sa = smem_u32(sm);
    uint32_t As = sa + 1024, Bs = sa + 1024 + 16384;

    int tilei = blockIdx.y;
    if (tilei >= g_ntiles) return;
    int e = g_tile_e[tilei], s0 = g_tile_s[tilei];
    int rows = min(BM, g_cnt[e] - s0);
    int hidbase = g_off[e] + s0;
    int N0 = blockIdx.x * 128;

    int tid = threadIdx.x, lane = tid & 31, wid = tid >> 5;
    int wm = wid >> 2, wn = wid & 3;

    if (tid < 128) {
        int idx = e * T_TOK + s0 + min(tid, rows - 1);
        rowTokS[tid] = g_tok[idx];
        rowWS[tid]   = g_w[idx];
    }
    __syncthreads();

    // B base pointer per expert / half
    const float* Bbase;
    int bn0;
    if (MODE == 0) {
        if (N0 < 1024) { Bbase = (e < NE) ? B0 + (size_t)e * 2048 * 1024 : B2; bn0 = N0; }
        else           { Bbase = (e < NE) ? B1 + (size_t)e * 2048 * 1024 : B3; bn0 = N0 - 1024; }
    } else {
        Bbase = (e < NE) ? B0 + (size_t)e * 1024 * 2048 : B1;
        bn0 = N0;
    }

    // per-thread load coordinates
    int aRow = tid >> 3, aC4 = (tid & 7) * 4;       // +32 per i
    int bK   = tid >> 5, bN4 = (tid & 31) * 4;      // +8 per i

    float4 fa[4], fb[4];
    // load chunk 0
    {
        #pragma unroll
        for (int i = 0; i < 4; i++) {
            int r = aRow + i * 32;
            if (MODE == 0) {
                int tok = rowTokS[r];
                fa[i] = *(const float4*)&x[(size_t)tok * ASTR + aC4];
            } else {
                int ar = hidbase + min(r, rows - 1);
                fa[i] = *(const float4*)&g_h[(size_t)ar * ASTR + aC4];
            }
            fb[i] = *(const float4*)&Bbase[(size_t)(bK + i * 8) * BSTR + bn0 + bN4];
        }
    }

    float acc[4][4][4];
    #pragma unroll
    for (int a = 0; a < 4; a++)
        #pragma unroll
        for (int b = 0; b < 4; b++)
            #pragma unroll
            for (int cc = 0; cc < 4; cc++) acc[a][b][cc] = 0.f;

    for (int c = 0; c < KCH; c++) {
        // stage regs -> smem (convert to bf16 hi/lo, swizzled)
        #pragma unroll
        for (int i = 0; i < 4; i++) {
            int r = aRow + i * 32;
            uint2 hi, lo;
            split4(fa[i], hi, lo);
            int sw = (r & 7) << 4;
            *(uint2*)(Asm + r * 128 + ((aC4 * 2)      ^ sw)) = hi;
            *(uint2*)(Asm + r * 128 + ((aC4 * 2 + 64) ^ sw)) = lo;
            int k = bK + i * 8;
            split4(fb[i], hi, lo);
            int swb = (k & 7) << 4;
            *(uint2*)(Bsm +        k * 256 + ((bN4 * 2) ^ swb)) = hi;
            *(uint2*)(Bsm + 8192 + k * 256 + ((bN4 * 2) ^ swb)) = lo;
        }
        __syncthreads();

        // prefetch next chunk
        if (c + 1 < KCH) {
            int k0 = (c + 1) * 32;
            #pragma unroll
            for (int i = 0; i < 4; i++) {
                int r = aRow + i * 32;
                if (MODE == 0) {
                    int tok = rowTokS[r];
                    fa[i] = *(const float4*)&x[(size_t)tok * ASTR + k0 + aC4];
                } else {
                    int ar = hidbase + min(r, rows - 1);
                    fa[i] = *(const float4*)&g_h[(size_t)ar * ASTR + k0 + aC4];
                }
                fb[i] = *(const float4*)&Bbase[(size_t)(k0 + bK + i * 8) * BSTR + bn0 + bN4];
            }
        }

        // compute: 2 k16 steps x 3 passes
        int lm = lane & 15, lkh = lane >> 4;
        #pragma unroll
        for (int ks = 0; ks < 2; ks++) {
            uint32_t Bh[2][4], Bl[2][4];
            #pragma unroll
            for (int pr = 0; pr < 2; pr++) {
                int k = ks * 16 + lm;
                int n = wn * 32 + pr * 16 + lkh * 8;
                uint32_t addr = Bs + k * 256 + ((n * 2) ^ ((k & 7) << 4));
                ldsm_x4_t(Bh[pr], addr);
                ldsm_x4_t(Bl[pr], addr + 8192);
            }
            #pragma unroll
            for (int mt = 0; mt < 4; mt++) {
                int m = wm * 64 + mt * 16 + lm;
                int boff = (lkh * 16 + ks * 32) ^ ((m & 7) << 4);
                uint32_t Ah[4], Al[4];
                ldsm_x4(Ah, As + m * 128 + boff);
                ldsm_x4(Al, As + m * 128 + (boff ^ 64));
                #pragma unroll
                for (int nt = 0; nt < 4; nt++) {
                    const uint32_t* bh = &Bh[nt >> 1][(nt & 1) * 2];
                    const uint32_t* bl = &Bl[nt >> 1][(nt & 1) * 2];
                    mma_bf16(acc[mt][nt], Ah, bh);
                    mma_bf16(acc[mt][nt], Al, bh);
                    mma_bf16(acc[mt][nt], Ah, bl);
                }
            }
        }
        __syncthreads();
    }

    // epilogue
    int gr = lane >> 2, gc = (lane & 3) * 2;
    #pragma unroll
    for (int mt = 0; mt < 4; mt++) {
        #pragma unroll
        for (int nt = 0; nt < 4; nt++) {
            int r0 = wm * 64 + mt * 16 + gr;
            int col = N0 + wn * 32 + nt * 8 + gc;
            if (MODE == 0) {
                size_t o = (size_t)(hidbase + r0) * 2048 + col;
                if (r0 < rows)
                    *(float2*)&g_gu[o] = make_float2(acc[mt][nt][0], acc[mt][nt][1]);
                if (r0 + 8 < rows)
                    *(float2*)&g_gu[o + 8 * 2048] = make_float2(acc[mt][nt][2], acc[mt][nt][3]);
            } else {
                if (r0 < rows) {
                    int tok = rowTokS[r0]; float w = rowWS[r0];
                    atomicAdd(&out[(size_t)tok * 2048 + col],     acc[mt][nt][0] * w);
                    atomicAdd(&out[(size_t)tok * 2048 + col + 1], acc[mt][nt][1] * w);
                }
                if (r0 + 8 < rows) {
                    int tok = rowTokS[r0 + 8]; float w = rowWS[r0 + 8];
                    atomicAdd(&out[(size_t)tok * 2048 + col],     acc[mt][nt][2] * w);
                    atomicAdd(&out[(size_t)tok * 2048 + col + 1], acc[mt][nt][3] * w);
                }
            }
        }
    }
}

// ===================== fuse: h = silu(g) * u =====================
__global__ void __launch_bounds__(256)
fuse_kernel() {
    int nrows = g_off[NE_TOT];
    int total = nrows * 256;   // float4 granules per row: 1024/4
    for (int idx = blockIdx.x * blockDim.x + threadIdx.x; idx < total;
         idx += gridDim.x * blockDim.x) {
        int r = idx >> 8, c4 = (idx & 255) * 4;
        float4 g = *(const float4*)&g_gu[(size_t)r * 2048 + c4];
        float4 u = *(const float4*)&g_gu[(size_t)r * 2048 + 1024 + c4];
        float4 h;
        h.x = (g.x / (1.f + __expf(-g.x))) * u.x;
        h.y = (g.y / (1.f + __expf(-g.y))) * u.y;
        h.z = (g.z / (1.f + __expf(-g.z))) * u.z;
        h.w = (g.w / (1.f + __expf(-g.w))) * u.w;
        *(float4*)&g_h[(size_t)r * 1024 + c4] = h;
    }
}

// ===================== launch =====================
extern "C" void kernel_launch(void* const* d_in, const int* in_sizes, int n_in,
                              void* d_out, int out_size) {
    const float* x    = (const float*)d_in[0];
    const float* rw   = (const float*)d_in[1];
    const float* bias = (const float*)d_in[2];
    const float* wg   = (const float*)d_in[3];
    const float* wu   = (const float*)d_in[4];
    const float* wd   = (const float*)d_in[5];
    const float* swg  = (const float*)d_in[6];
    const float* swu  = (const float*)d_in[7];
    const float* swd  = (const float*)d_in[8];
    float* out = (float*)d_out;

    cudaMemsetAsync(d_out, 0, (size_t)out_size * sizeof(float));
    zero_kernel<<<1, 64>>>();
    router_kernel<<<T_TOK / 8, 256>>>(x, rw, bias);
    build_tiles_kernel<<<1, 32>>>();

    moe_gemm<0><<<dim3(16, MAXTILES), 256>>>(x, wg, wu, swg, swu, nullptr);
    fuse_kernel<<<1024, 256>>>();
    moe_gemm<1><<<dim3(16, MAXTILES), 256>>>(x, wd, swd, nullptr, nullptr, out);
}

// round 5
// speedup vs baseline: 2.4585x; 1.0220x over previous
#include <cuda_runtime.h>
#include <cuda_bf16.h>
#include <math.h>
#include <stdint.h>

#define T_TOK 2048
#define HID   2048
#define INTD  1024
#define NE    32
#define NE_TOT 33
#define TOPK  4
#define MAXTILES 128
#define BM    128
#define ROWS_MAX 10368

// ===================== device scratch =====================
__device__ int   g_cnt[NE_TOT];
__device__ int   g_tok[NE_TOT * T_TOK];
__device__ float g_w  [NE_TOT * T_TOK];
__device__ int   g_off[NE_TOT + 1];
__device__ int   g_tile_e[MAXTILES];
__device__ int   g_tile_s[MAXTILES];
__device__ int   g_ntiles;
// intermediate h = silu(g)*u, split bf16 planes
__device__ __align__(16) __nv_bfloat16 g_hhi[(size_t)ROWS_MAX * INTD];
__device__ __align__(16) __nv_bfloat16 g_hlo[(size_t)ROWS_MAX * INTD];

// ===================== PTX helpers (family-level, sm_80+) =====================
__device__ __forceinline__ uint32_t smem_u32(const void* p) {
    uint32_t a;
    asm("{ .reg .u64 t; cvta.to.shared.u64 t, %1; cvt.u32.u64 %0, t; }" : "=r"(a) : "l"(p));
    return a;
}
__device__ __forceinline__ void ldsm_x4(uint32_t* r, uint32_t a) {
    asm volatile("ldmatrix.sync.aligned.m8n8.x4.shared.b16 {%0,%1,%2,%3}, [%4];"
                 : "=r"(r[0]), "=r"(r[1]), "=r"(r[2]), "=r"(r[3]) : "r"(a));
}
__device__ __forceinline__ void ldsm_x4_t(uint32_t* r, uint32_t a) {
    asm volatile("ldmatrix.sync.aligned.m8n8.x4.trans.shared.b16 {%0,%1,%2,%3}, [%4];"
                 : "=r"(r[0]), "=r"(r[1]), "=r"(r[2]), "=r"(r[3]) : "r"(a));
}
__device__ __forceinline__ void mma_bf16(float* c, const uint32_t* a, const uint32_t* b) {
    asm volatile("mma.sync.aligned.m16n8k16.row.col.f32.bf16.bf16.f32 "
        "{%0,%1,%2,%3}, {%4,%5,%6,%7}, {%8,%9}, {%0,%1,%2,%3};"
        : "+f"(c[0]), "+f"(c[1]), "+f"(c[2]), "+f"(c[3])
        : "r"(a[0]), "r"(a[1]), "r"(a[2]), "r"(a[3]), "r"(b[0]), "r"(b[1]));
}
__device__ __forceinline__ void split4(float4 f, uint2& hi, uint2& lo) {
    __nv_bfloat16 a0 = __float2bfloat16(f.x), a1 = __float2bfloat16(f.y);
    __nv_bfloat16 a2 = __float2bfloat16(f.z), a3 = __float2bfloat16(f.w);
    __nv_bfloat16 b0 = __float2bfloat16(f.x - __bfloat162float(a0));
    __nv_bfloat16 b1 = __float2bfloat16(f.y - __bfloat162float(a1));
    __nv_bfloat16 b2 = __float2bfloat16(f.z - __bfloat162float(a2));
    __nv_bfloat16 b3 = __float2bfloat16(f.w - __bfloat162float(a3));
    __nv_bfloat162 h01(a0, a1), h23(a2, a3), l01(b0, b1), l23(b2, b3);
    hi = make_uint2(*(uint32_t*)&h01, *(uint32_t*)&h23);
    lo = make_uint2(*(uint32_t*)&l01, *(uint32_t*)&l23);
}

// ===================== small kernels =====================
__global__ void zero_kernel() {
    int t = threadIdx.x;
    if (t < NE) g_cnt[t] = 0;
    if (t == NE) g_cnt[NE] = T_TOK;
}

__global__ void __launch_bounds__(256)
router_kernel(const float* __restrict__ x,
              const float* __restrict__ rw,
              const float* __restrict__ bias) {
    __shared__ float rwS[32][65];
    __shared__ float xS[8][64];
    int warp = threadIdx.x >> 5, lane = threadIdx.x & 31;
    int t = blockIdx.x * 8 + warp;

    float acc = 0.f;
    for (int h0 = 0; h0 < HID; h0 += 64) {
        __syncthreads();
        for (int i = threadIdx.x; i < 32 * 64; i += 256) {
            int e = i >> 6, j = i & 63;
            rwS[e][j] = rw[e * HID + h0 + j];
        }
        xS[warp][lane]      = x[(size_t)t * HID + h0 + lane];
        xS[warp][lane + 32] = x[(size_t)t * HID + h0 + 32 + lane];
        __syncthreads();
        #pragma unroll 8
        for (int j = 0; j < 64; j++)
            acc += xS[warp][j] * rwS[lane][j];
    }
    float score = 1.f / (1.f + __expf(-acc));
    float selv  = score + bias[lane];

    int   picks[TOPK];
    float pw[TOPK];
    float wsum = 0.f;
    #pragma unroll
    for (int k = 0; k < TOPK; k++) {
        float v = selv; int idx = lane;
        #pragma unroll
        for (int o = 16; o > 0; o >>= 1) {
            float v2 = __shfl_xor_sync(0xFFFFFFFFu, v, o);
            int   i2 = __shfl_xor_sync(0xFFFFFFFFu, idx, o);
            if (v2 > v || (v2 == v && i2 < idx)) { v = v2; idx = i2; }
        }
        picks[k] = idx;
        float w = __shfl_sync(0xFFFFFFFFu, score, idx);
        pw[k] = w; wsum += w;
        if (lane == idx) selv = -INFINITY;
    }
    if (lane == 0) {
        float inv = 1.f / (wsum + 1e-20f);
        #pragma unroll
        for (int k = 0; k < TOPK; k++) {
            int e = picks[k];
            int pos = atomicAdd(&g_cnt[e], 1);
            g_tok[e * T_TOK + pos] = t;
            g_w  [e * T_TOK + pos] = pw[k] * inv;
        }
        g_tok[NE * T_TOK + t] = t;
        g_w  [NE * T_TOK + t] = 1.0f;
    }
}

__global__ void build_tiles_kernel() {
    if (threadIdx.x == 0 && blockIdx.x == 0) {
        int off = 0, nt = 0;
        for (int e = 0; e < NE_TOT; e++) {
            g_off[e] = off;
            int c = g_cnt[e];
            for (int s = 0; s < c && nt < MAXTILES; s += BM) {
                g_tile_e[nt] = e; g_tile_s[nt] = s; nt++;
            }
            off += c;
        }
        g_off[NE_TOT] = off;
        g_ntiles = nt;
    }
}

// ===================== gate+up grouped GEMM with fused SiLU =====================
// CTA: 128 rows x 64 intermediate cols (gate AND up). Warps wn 0,1 = gate,
// wn 2,3 = up (same cols). Double-buffered smem, 1 sync/chunk.
// stage layout: A[16KB: 128r x (32hi+32lo) bf16] ; B[16KB: ghi|glo|uhi|ulo 4KB each]
#define PIPE_SMEM (1024 + 2 * 32768)
__global__ void __launch_bounds__(256, 1)
gu_gemm(const float* __restrict__ x,
        const float* __restrict__ wgR, const float* __restrict__ wuR,
        const float* __restrict__ wgS, const float* __restrict__ wuS) {
    extern __shared__ char sm[];
    uint32_t sa = smem_u32(sm);
    int* rowTokS = (int*)sm;

    int tilei = blockIdx.y;
    if (tilei >= g_ntiles) return;
    int e = g_tile_e[tilei], s0 = g_tile_s[tilei];
    int rows = min(BM, g_cnt[e] - s0);
    int hidbase = g_off[e] + s0;
    int N0 = blockIdx.x * 64;

    int tid = threadIdx.x, lane = tid & 31, wid = tid >> 5;
    int wm = wid >> 2, wn = wid & 3;

    if (tid < 128)
        rowTokS[tid] = g_tok[e * T_TOK + s0 + min(tid, rows - 1)];
    __syncthreads();

    const float* gptr = (e < NE) ? wgR + (size_t)e * HID * INTD : wgS;
    const float* uptr = (e < NE) ? wuR + (size_t)e * HID * INTD : wuS;

    int aRow = tid >> 3, aC4 = (tid & 7) * 4;
    int bK = tid >> 4,  bN4 = (tid & 15) * 4;
    int tokR[4];
    #pragma unroll
    for (int i = 0; i < 4; i++) tokR[i] = rowTokS[aRow + 32 * i];

    float4 fa[4], fg[2], fu[2];
    #pragma unroll
    for (int i = 0; i < 4; i++)
        fa[i] = *(const float4*)&x[(size_t)tokR[i] * HID + aC4];
    #pragma unroll
    for (int i = 0; i < 2; i++) {
        int k = bK + 16 * i;
        fg[i] = *(const float4*)&gptr[(size_t)k * INTD + N0 + bN4];
        fu[i] = *(const float4*)&uptr[(size_t)k * INTD + N0 + bN4];
    }

    float acc[4][4][4];
    #pragma unroll
    for (int a = 0; a < 4; a++)
        #pragma unroll
        for (int b = 0; b < 4; b++)
            #pragma unroll
            for (int f = 0; f < 4; f++) acc[a][b][f] = 0.f;

    const int KCH = HID / 32;
    int lm = lane & 15, lkh = lane >> 4;
    int slab = (wn >> 1) * 8192;

    for (int c = 0; c < KCH; c++) {
        char* base = sm + 1024 + (c & 1) * 32768;
        uint32_t As = sa + 1024 + (c & 1) * 32768;
        uint32_t Bs = As + 16384;
        char* Asm = base;
        char* Bsm = base + 16384;

        #pragma unroll
        for (int i = 0; i < 4; i++) {
            int r = aRow + 32 * i; int sw = (r & 7) << 4;
            uint2 hi, lo; split4(fa[i], hi, lo);
            *(uint2*)(Asm + r * 128 + ((aC4 * 2)      ^ sw)) = hi;
            *(uint2*)(Asm + r * 128 + ((aC4 * 2 + 64) ^ sw)) = lo;
        }
        #pragma unroll
        for (int i = 0; i < 2; i++) {
            int k = bK + 16 * i; int swb = (k & 7) << 4;
            uint2 hi, lo; split4(fg[i], hi, lo);
            *(uint2*)(Bsm +         k * 128 + ((bN4 * 2) ^ swb)) = hi;
            *(uint2*)(Bsm + 4096  + k * 128 + ((bN4 * 2) ^ swb)) = lo;
            split4(fu[i], hi, lo);
            *(uint2*)(Bsm + 8192  + k * 128 + ((bN4 * 2) ^ swb)) = hi;
            *(uint2*)(Bsm + 12288 + k * 128 + ((bN4 * 2) ^ swb)) = lo;
        }
        __syncthreads();

        if (c + 1 < KCH) {
            int k0 = (c + 1) * 32;
            #pragma unroll
            for (int i = 0; i < 4; i++)
                fa[i] = *(const float4*)&x[(size_t)tokR[i] * HID + k0 + aC4];
            #pragma unroll
            for (int i = 0; i < 2; i++) {
                int k = k0 + bK + 16 * i;
                fg[i] = *(const float4*)&gptr[(size_t)k * INTD + N0 + bN4];
                fu[i] = *(const float4*)&uptr[(size_t)k * INTD + N0 + bN4];
            }
        }

        #pragma unroll
        for (int ks = 0; ks < 2; ks++) {
            uint32_t Bh[2][4], Bl[2][4];
            #pragma unroll
            for (int pr = 0; pr < 2; pr++) {
                int k = ks * 16 + lm;
                int n = (wn & 1) * 32 + pr * 16 + lkh * 8;
                uint32_t ad = Bs + slab + k * 128 + ((n * 2) ^ ((k & 7) << 4));
                ldsm_x4_t(Bh[pr], ad);
                ldsm_x4_t(Bl[pr], ad + 4096);
            }
            #pragma unroll
            for (int mt = 0; mt < 4; mt++) {
                int m = wm * 64 + mt * 16 + lm;
                int boff = (lkh * 16 + ks * 32) ^ ((m & 7) << 4);
                uint32_t Ah[4], Al[4];
                ldsm_x4(Ah, As + m * 128 + boff);
                ldsm_x4(Al, As + m * 128 + (boff ^ 64));
                #pragma unroll
                for (int nt = 0; nt < 4; nt++) {
                    const uint32_t* bh = &Bh[nt >> 1][(nt & 1) * 2];
                    const uint32_t* bl = &Bl[nt >> 1][(nt & 1) * 2];
                    mma_bf16(acc[mt][nt], Ah, bh);
                    mma_bf16(acc[mt][nt], Al, bh);
                    mma_bf16(acc[mt][nt], Ah, bl);
                }
            }
        }
    }
    __syncthreads();

    // ---- epilogue: up warps export accs; gate warps fuse + write bf16 planes
    float* scratch = (float*)(sm + 1024);   // 4 warps x 32 lanes x 64 f = 32KB
    int gr = lane >> 2, gc = (lane & 3) * 2;
    if (wn >= 2) {
        int base = ((wm * 2 + (wn - 2)) * 32 + lane) * 64;
        #pragma unroll
        for (int mt = 0; mt < 4; mt++)
            #pragma unroll
            for (int nt = 0; nt < 4; nt++)
                #pragma unroll
                for (int f = 0; f < 4; f++)
                    scratch[base + (mt * 4 + nt) * 4 + f] = acc[mt][nt][f];
    }
    __syncthreads();
    if (wn < 2) {
        int base = ((wm * 2 + wn) * 32 + lane) * 64;
        #pragma unroll
        for (int mt = 0; mt < 4; mt++) {
            #pragma unroll
            for (int nt = 0; nt < 4; nt++) {
                int col = N0 + wn * 32 + nt * 8 + gc;
                float u0 = scratch[base + (mt * 4 + nt) * 4 + 0];
                float u1 = scratch[base + (mt * 4 + nt) * 4 + 1];
                float u2 = scratch[base + (mt * 4 + nt) * 4 + 2];
                float u3 = scratch[base + (mt * 4 + nt) * 4 + 3];
                #pragma unroll
                for (int p = 0; p < 2; p++) {
                    int r = wm * 64 + mt * 16 + gr + p * 8;
                    if (r < rows) {
                        float g0 = acc[mt][nt][2 * p], g1 = acc[mt][nt][2 * p + 1];
                        float uu0 = p ? u2 : u0, uu1 = p ? u3 : u1;
                        float h0 = (g0 / (1.f + __expf(-g0))) * uu0;
                        float h1 = (g1 / (1.f + __expf(-g1))) * uu1;
                        __nv_bfloat16 h0h = __float2bfloat16(h0);
                        __nv_bfloat16 h1h = __float2bfloat16(h1);
                        __nv_bfloat16 h0l = __float2bfloat16(h0 - __bfloat162float(h0h));
                        __nv_bfloat16 h1l = __float2bfloat16(h1 - __bfloat162float(h1h));
                        size_t o = (size_t)(hidbase + r) * INTD + col;
                        __nv_bfloat162 hh(h0h, h1h), ll(h0l, h1l);
                        *(uint32_t*)&g_hhi[o] = *(uint32_t*)&hh;
                        *(uint32_t*)&g_hlo[o] = *(uint32_t*)&ll;
                    }
                }
            }
        }
    }
}

// ===================== down grouped GEMM + weighted scatter =====================
// CTA: 128 rows x 128 out cols. A from bf16 planes (no conversion).
// stage: A[16KB] ; B[16KB: hi 8KB | lo 8KB, rows 256B]
__global__ void __launch_bounds__(256, 1)
dn_gemm(const float* __restrict__ wdR, const float* __restrict__ wdS,
        float* __restrict__ out) {
    extern __shared__ char sm[];
    uint32_t sa = smem_u32(sm);
    int* rowTokS = (int*)sm;
    float* rowWS = (float*)(sm + 512);

    int tilei = blockIdx.y;
    if (tilei >= g_ntiles) return;
    int e = g_tile_e[tilei], s0 = g_tile_s[tilei];
    int rows = min(BM, g_cnt[e] - s0);
    int hidbase = g_off[e] + s0;
    int N0 = blockIdx.x * 128;

    int tid = threadIdx.x, lane = tid & 31, wid = tid >> 5;
    int wm = wid >> 2, wn = wid & 3;

    if (tid < 128) {
        int idx = e * T_TOK + s0 + min(tid, rows - 1);
        rowTokS[tid] = g_tok[idx];
        rowWS[tid]   = g_w[idx];
    }
    __syncthreads();

    const float* wd = (e < NE) ? wdR + (size_t)e * INTD * HID : wdS;

    // A: j = tid&3 (16B granule in k), rows r = tid>>2 + 64*i
    int aJ = tid & 3;
    int arR[2];
    #pragma unroll
    for (int i = 0; i < 2; i++)
        arR[i] = hidbase + min((tid >> 2) + 64 * i, rows - 1);
    int bK = tid >> 5, bN4 = (tid & 31) * 4;

    uint4 ha[2], la[2];
    float4 fb[4];
    #pragma unroll
    for (int i = 0; i < 2; i++) {
        ha[i] = *(const uint4*)&g_hhi[(size_t)arR[i] * INTD + aJ * 8];
        la[i] = *(const uint4*)&g_hlo[(size_t)arR[i] * INTD + aJ * 8];
    }
    #pragma unroll
    for (int i = 0; i < 4; i++)
        fb[i] = *(const float4*)&wd[(size_t)(bK + 8 * i) * HID + N0 + bN4];

    float acc[4][4][4];
    #pragma unroll
    for (int a = 0; a < 4; a++)
        #pragma unroll
        for (int b = 0; b < 4; b++)
            #pragma unroll
            for (int f = 0; f < 4; f++) acc[a][b][f] = 0.f;

    const int KCH = INTD / 32;
    int lm = lane & 15, lkh = lane >> 4;

    for (int c = 0; c < KCH; c++) {
        char* base = sm + 1024 + (c & 1) * 32768;
        uint32_t As = sa + 1024 + (c & 1) * 32768;
        uint32_t Bs = As + 16384;
        char* Asm = base;
        char* Bsm = base + 16384;

        #pragma unroll
        for (int i = 0; i < 2; i++) {
            int r = (tid >> 2) + 64 * i; int sw = (r & 7) << 4;
            *(uint4*)(Asm + r * 128 + ((aJ * 16)      ^ sw)) = ha[i];
            *(uint4*)(Asm + r * 128 + ((aJ * 16 + 64) ^ sw)) = la[i];
        }
        #pragma unroll
        for (int i = 0; i < 4; i++) {
            int k = bK + 8 * i; int swb = (k & 7) << 4;
            uint2 hi, lo; split4(fb[i], hi, lo);
            *(uint2*)(Bsm +        k * 256 + ((bN4 * 2) ^ swb)) = hi;
            *(uint2*)(Bsm + 8192 + k * 256 + ((bN4 * 2) ^ swb)) = lo;
        }
        __syncthreads();

        if (c + 1 < KCH) {
            int k0 = (c + 1) * 32;
            #pragma unroll
            for (int i = 0; i < 2; i++) {
                ha[i] = *(const uint4*)&g_hhi[(size_t)arR[i] * INTD + k0 + aJ * 8];
                la[i] = *(const uint4*)&g_hlo[(size_t)arR[i] * INTD + k0 + aJ * 8];
            }
            #pragma unroll
            for (int i = 0; i < 4; i++)
                fb[i] = *(const float4*)&wd[(size_t)(k0 + bK + 8 * i) * HID + N0 + bN4];
        }

        #pragma unroll
        for (int ks = 0; ks < 2; ks++) {
            uint32_t Bh[2][4], Bl[2][4];
            #pragma unroll
            for (int pr = 0; pr < 2; pr++) {
                int k = ks * 16 + lm;
                int n = wn * 32 + pr * 16 + lkh * 8;
                uint32_t ad = Bs + k * 256 + ((n * 2) ^ ((k & 7) << 4));
                ldsm_x4_t(Bh[pr], ad);
                ldsm_x4_t(Bl[pr], ad + 8192);
            }
            #pragma unroll
            for (int mt = 0; mt < 4; mt++) {
                int m = wm * 64 + mt * 16 + lm;
                int boff = (lkh * 16 + ks * 32) ^ ((m & 7) << 4);
                uint32_t Ah[4], Al[4];
                ldsm_x4(Ah, As + m * 128 + boff);
                ldsm_x4(Al, As + m * 128 + (boff ^ 64));
                #pragma unroll
                for (int nt = 0; nt < 4; nt++) {
                    const uint32_t* bh = &Bh[nt >> 1][(nt & 1) * 2];
                    const uint32_t* bl = &Bl[nt >> 1][(nt & 1) * 2];
                    mma_bf16(acc[mt][nt], Ah, bh);
                    mma_bf16(acc[mt][nt], Al, bh);
                    mma_bf16(acc[mt][nt], Ah, bl);
                }
            }
        }
    }

    int gr = lane >> 2, gc = (lane & 3) * 2;
    #pragma unroll
    for (int mt = 0; mt < 4; mt++) {
        #pragma unroll
        for (int nt = 0; nt < 4; nt++) {
            int r0 = wm * 64 + mt * 16 + gr;
            int col = N0 + wn * 32 + nt * 8 + gc;
            if (r0 < rows) {
                int tok = rowTokS[r0]; float w = rowWS[r0];
                atomicAdd(&out[(size_t)tok * HID + col],     acc[mt][nt][0] * w);
                atomicAdd(&out[(size_t)tok * HID + col + 1], acc[mt][nt][1] * w);
            }
            if (r0 + 8 < rows) {
                int tok = rowTokS[r0 + 8]; float w = rowWS[r0 + 8];
                atomicAdd(&out[(size_t)tok * HID + col],     acc[mt][nt][2] * w);
                atomicAdd(&out[(size_t)tok * HID + col + 1], acc[mt][nt][3] * w);
            }
        }
    }
}

// ===================== launch =====================
extern "C" void kernel_launch(void* const* d_in, const int* in_sizes, int n_in,
                              void* d_out, int out_size) {
    const float* x    = (const float*)d_in[0];
    const float* rw   = (const float*)d_in[1];
    const float* bias = (const float*)d_in[2];
    const float* wg   = (const float*)d_in[3];
    const float* wu   = (const float*)d_in[4];
    const float* wd   = (const float*)d_in[5];
    const float* swg  = (const float*)d_in[6];
    const float* swu  = (const float*)d_in[7];
    const float* swd  = (const float*)d_in[8];
    float* out = (float*)d_out;

    cudaFuncSetAttribute(gu_gemm, cudaFuncAttributeMaxDynamicSharedMemorySize, PIPE_SMEM);
    cudaFuncSetAttribute(dn_gemm, cudaFuncAttributeMaxDynamicSharedMemorySize, PIPE_SMEM);

    cudaMemsetAsync(d_out, 0, (size_t)out_size * sizeof(float));
    zero_kernel<<<1, 64>>>();
    router_kernel<<<T_TOK / 8, 256>>>(x, rw, bias);
    build_tiles_kernel<<<1, 32>>>();

    gu_gemm<<<dim3(INTD / 64, MAXTILES), 256, PIPE_SMEM>>>(x, wg, wu, swg, swu);
    dn_gemm<<<dim3(HID / 128, MAXTILES), 256, PIPE_SMEM>>>(wd, swd, out);
}